// round 16
// baseline (speedup 1.0000x reference)
#include <cuda_runtime.h>
#include <cuda_fp16.h>
#include <cstdint>

// ===========================================================================
// MyRGCNConv, single-term fp16, bulk-copy GEMM:
//  Phase 0a: W -> g_bt fp16, PRE-TILED [2 nblk][64 kt][128 rows x 80B]
//  Phase 0b: x f32 -> g_xh fp16
//  Phase 0c: per-center counting sort by relation; g_snode = node*256 offsets
//  Phase 1:  agg, warp-per-center, LDG.128 gather, half2 accum, writes A
//            PRE-TILED [392 blk][64 kt][128 rows x 80B]
//  Phase 2:  GEMM 128x128 (grid.y=2), 4 warps of 64x64, BK=32, 3-stage;
//            each stage filled by 2 cp.async.bulk (10240B) + mbarrier.
// ===========================================================================

#define DFEAT 256
#define NRELS 8
#define KDIM  2048
#define EMAX  1048576
#define CMAX  50048
#define MAXM  50176
#define NMAX  50176

#define ROWB    80u
#define CHUNKB  10240u                 // 128 rows x 80B, one (blk, kt) tile
#define NKT     64                     // K chunks of 32

// A tiled: [MAXM/128][NKT][CHUNKB]  = 392*64*10240 = 256,901,120 B
__device__ __align__(16) unsigned char g_at[(size_t)(MAXM / 128) * NKT * CHUNKB];
// B tiled: [2][NKT][CHUNKB] = 1,310,720 B
__device__ __align__(16) unsigned char g_bt[(size_t)2 * NKT * CHUNKB];
__device__ __align__(16) __half g_xh[(size_t)NMAX * DFEAT];
__device__ int   g_snode[EMAX];
__device__ uint2 g_roff[CMAX];

// ---------------------------------------------------------------------------
__device__ __forceinline__ uint32_t smem_u32(const void* p) {
    uint32_t a;
    asm("{ .reg .u64 t; cvta.to.shared.u64 t, %1; cvt.u32.u64 %0, t; }"
        : "=r"(a) : "l"(p));
    return a;
}
__device__ __forceinline__ void ldm_x4(uint32_t& r0, uint32_t& r1,
                                       uint32_t& r2, uint32_t& r3, uint32_t a) {
    asm volatile("ldmatrix.sync.aligned.m8n8.x4.shared.b16 {%0,%1,%2,%3}, [%4];"
                 : "=r"(r0), "=r"(r1), "=r"(r2), "=r"(r3) : "r"(a));
}
__device__ __forceinline__ void mma_f16(float* c, const uint32_t* a,
                                        uint32_t b0, uint32_t b1) {
    asm volatile(
        "mma.sync.aligned.m16n8k16.row.col.f32.f16.f16.f32 "
        "{%0,%1,%2,%3}, {%4,%5,%6,%7}, {%8,%9}, {%0,%1,%2,%3};"
        : "+f"(c[0]), "+f"(c[1]), "+f"(c[2]), "+f"(c[3])
        : "r"(a[0]), "r"(a[1]), "r"(a[2]), "r"(a[3]), "r"(b0), "r"(b1));
}
__device__ __forceinline__ void bulk_g2s(uint32_t dst, const void* src,
                                         uint32_t bytes, uint32_t mbar) {
    asm volatile(
        "cp.async.bulk.shared::cluster.global.mbarrier::complete_tx::bytes "
        "[%0], [%1], %2, [%3];"
        :: "r"(dst), "l"(src), "r"(bytes), "r"(mbar) : "memory");
}
__device__ __forceinline__ void mbar_expect(uint32_t mbar, uint32_t bytes) {
    asm volatile("mbarrier.arrive.expect_tx.shared.b64 _, [%0], %1;"
                 :: "r"(mbar), "r"(bytes) : "memory");
}
__device__ __forceinline__ void mbar_wait(uint32_t mbar, uint32_t phase) {
    asm volatile(
        "{\n\t.reg .pred P;\n\t"
        "WL_%=:\n\t"
        "mbarrier.try_wait.parity.shared::cta.b64 P, [%0], %1;\n\t"
        "@P bra.uni WD_%=;\n\t"
        "bra.uni WL_%=;\n\t"
        "WD_%=:\n\t}"
        :: "r"(mbar), "r"(phase) : "memory");
}

// ---------------------------------------------------------------------------
// Phase 0a: weight transpose to fp16, tiled layout
// ---------------------------------------------------------------------------
__global__ void __launch_bounds__(256) wsplit_kernel(const float* __restrict__ w) {
    int i = blockIdx.x * 256 + threadIdx.x;   // over 256*2048
    int n = i >> 11;
    int k = i & 2047;
    const __half h = __float2half(w[(size_t)k * DFEAT + n]);
    const int nblk = n >> 7, row = n & 127, kt = k >> 5, col = k & 31;
    *(__half*)(g_bt + ((size_t)nblk * NKT + kt) * CHUNKB + row * ROWB + col * 2) = h;
}

// ---------------------------------------------------------------------------
// Phase 0b: x f32 -> fp16
// ---------------------------------------------------------------------------
__global__ void __launch_bounds__(256) xconv_kernel(const float* __restrict__ x,
                                                    int n2) {
    int i = blockIdx.x * 256 + threadIdx.x;
    if (i >= n2) return;
    const float2 v = ((const float2*)x)[i];
    __half2 h; h.x = __float2half(v.x); h.y = __float2half(v.y);
    ((__half2*)g_xh)[i] = h;
}

// ---------------------------------------------------------------------------
// Phase 0c: per-center counting sort by relation; emit element offsets
// ---------------------------------------------------------------------------
__global__ void __launch_bounds__(256) sort_kernel(
    const int* __restrict__ ptr,
    const int* __restrict__ idx,
    const int* __restrict__ rel,
    int C)
{
    const int c = blockIdx.x * 256 + threadIdx.x;
    if (c >= C) return;
    const int beg = ptr[c];
    const int end = ptr[c + 1];

    int cnt[NRELS];
#pragma unroll
    for (int r = 0; r < NRELS; ++r) cnt[r] = 0;
    for (int e = beg; e < end; ++e) {
        const int re = __ldg(rel + e);
#pragma unroll
        for (int r = 0; r < NRELS; ++r) cnt[r] += (re == r);
    }
    int st[NRELS];
    int p = 0;
#pragma unroll
    for (int r = 0; r < NRELS; ++r) { st[r] = p; p += cnt[r]; }

    uint2 pk;
    pk.x = (uint32_t)st[0] | ((uint32_t)st[1] << 8) |
           ((uint32_t)st[2] << 16) | ((uint32_t)st[3] << 24);
    pk.y = (uint32_t)st[4] | ((uint32_t)st[5] << 8) |
           ((uint32_t)st[6] << 16) | ((uint32_t)st[7] << 24);
    g_roff[c] = pk;

    int pos[NRELS];
#pragma unroll
    for (int r = 0; r < NRELS; ++r) pos[r] = st[r];
    for (int e = beg; e < end; ++e) {
        const int re = __ldg(rel + e);
        int off = 0;
#pragma unroll
        for (int r = 0; r < NRELS; ++r) if (re == r) off = pos[r]++;
        g_snode[beg + off] = __ldg(idx + e) << 8;   // pre-scaled (x256)
    }
}

// ---------------------------------------------------------------------------
// Phase 1: aggregation, warp-per-center, half2 accum, tiled A output.
// Element (c, k=r*256+fo): blk=c>>7, row=c&127, kt=r*8+(fo>>5), col=fo&31.
// ---------------------------------------------------------------------------
__global__ void __launch_bounds__(128) agg_kernel(
    const int* __restrict__ ptr,
    int C)
{
    const int warp = threadIdx.x >> 5;
    const int lane = threadIdx.x & 31;
    const int c = blockIdx.x * 4 + warp;
    if (c >= C) return;

    const int beg = __ldg(ptr + c);
    const int deg = __ldg(ptr + c + 1) - beg;
    const uint2 ro = __ldg(&g_roff[c]);
    const int fo = lane * 8;
    const int blk = c >> 7, row = c & 127;
    unsigned char* abase = g_at + (size_t)blk * NKT * CHUNKB
                         + (size_t)row * ROWB + (fo & 31) * 2;
    const int kt0 = fo >> 5;            // 0..7

#pragma unroll
    for (int r = 0; r < NRELS; ++r) {
        const int js = (int)(((r < 4 ? ro.x : ro.y) >> ((r & 3) * 8)) & 0xFF);
        const int je = (r == 7) ? deg
            : (int)(((r + 1 < 4 ? ro.x : ro.y) >> (((r + 1) & 3) * 8)) & 0xFF);
        __half2 s0 = __half2half2(__ushort_as_half(0));
        __half2 s1 = s0, s2 = s0, s3 = s0;
#pragma unroll 2
        for (int j = js; j < je; ++j) {
            const int off = __ldg(&g_snode[beg + j]);
            const uint4 v = __ldg((const uint4*)(g_xh + off + fo));
            s0 = __hadd2(s0, *(const __half2*)&v.x);
            s1 = __hadd2(s1, *(const __half2*)&v.y);
            s2 = __hadd2(s2, *(const __half2*)&v.z);
            s3 = __hadd2(s3, *(const __half2*)&v.w);
        }
        uint4 o;
        o.x = *(uint32_t*)&s0; o.y = *(uint32_t*)&s1;
        o.z = *(uint32_t*)&s2; o.w = *(uint32_t*)&s3;
        *(uint4*)(abase + (size_t)(r * 8 + kt0) * CHUNKB) = o;
    }
}

// ---------------------------------------------------------------------------
// Phase 2: GEMM  out[M,256] = A * Bt^T, / deg.
// CTA 128x128 (grid.y=2), BK=32, 128 threads = 4 warps of 64x64, 3-stage.
// Stage fill: tid0 issues expect_tx + 2 cp.async.bulk of 10240B each.
// ---------------------------------------------------------------------------
#define BM     128
#define OFF_ST 128u                    // stages start after mbar area
#define STAGE  20480u
#define NSTG   3
#define SMEMSZ (OFF_ST + NSTG * STAGE) // 61568 bytes

__global__ void __launch_bounds__(128, 2) gemm_kernel(
    const int* __restrict__ ptr,
    float*     __restrict__ out,
    int C)
{
    extern __shared__ char smem[];
    const uint32_t sbase = smem_u32(smem);
    const int tid  = threadIdx.x;
    const int lane = tid & 31;
    const int wid  = tid >> 5;
    const int bm   = blockIdx.x * BM;
    const int nblk = blockIdx.y;            // 0 or 1

    const int warp_m = (wid & 1) * 64;
    const int warp_n = (wid >> 1) * 64;

    const unsigned char* Abase = g_at + (size_t)(bm >> 7) * NKT * CHUNKB;
    const unsigned char* Bbase = g_bt + (size_t)nblk * NKT * CHUNKB;

    // mbarriers (one per stage)
    if (tid == 0) {
#pragma unroll
        for (int s = 0; s < NSTG; ++s)
            asm volatile("mbarrier.init.shared.b64 [%0], %1;"
                         :: "r"(sbase + s * 8), "r"(1u) : "memory");
    }
    __syncthreads();

#define ISSUE_STAGE(kt)                                                         \
    do {                                                                        \
        const int      s_  = (kt) % NSTG;                                       \
        const uint32_t mb_ = sbase + s_ * 8;                                    \
        const uint32_t d_  = sbase + OFF_ST + (uint32_t)s_ * STAGE;             \
        mbar_expect(mb_, 2u * CHUNKB);                                          \
        bulk_g2s(d_,          Abase + (size_t)(kt) * CHUNKB, CHUNKB, mb_);      \
        bulk_g2s(d_ + CHUNKB, Bbase + (size_t)(kt) * CHUNKB, CHUNKB, mb_);      \
    } while (0)

    float acc[4][8][4];
#pragma unroll
    for (int i = 0; i < 4; ++i)
#pragma unroll
        for (int j = 0; j < 8; ++j)
#pragma unroll
            for (int q = 0; q < 4; ++q) acc[i][j][q] = 0.f;

    const uint32_t a_roff = (uint32_t)(warp_m + (lane & 15)) * ROWB +
                            (((uint32_t)lane >> 4) & 1) * 16;
    const uint32_t b_roff = (uint32_t)(warp_n + (((lane >> 4) & 1) * 8) + (lane & 7)) * ROWB +
                            (((uint32_t)lane >> 3) & 1) * 16;

    if (tid == 0) { ISSUE_STAGE(0); ISSUE_STAGE(1); }

    for (int kt = 0; kt < NKT; ++kt) {
        __syncthreads();               // all warps done with stage (kt-1)%3
        if (tid == 0 && kt + 2 < NKT) ISSUE_STAGE(kt + 2);

        mbar_wait(sbase + (kt % NSTG) * 8, (uint32_t)((kt / NSTG) & 1));

        const uint32_t sb = sbase + OFF_ST + (uint32_t)(kt % NSTG) * STAGE;
#pragma unroll
        for (int kf = 0; kf < 2; ++kf) {
            const uint32_t kfo = (uint32_t)kf * 32;

            uint32_t a[4][4], b[4][4];
#pragma unroll
            for (int mf = 0; mf < 4; ++mf)
                ldm_x4(a[mf][0], a[mf][1], a[mf][2], a[mf][3],
                       sb + a_roff + (uint32_t)mf * 16 * ROWB + kfo);
#pragma unroll
            for (int np = 0; np < 4; ++np)
                ldm_x4(b[np][0], b[np][1], b[np][2], b[np][3],
                       sb + CHUNKB + b_roff + (uint32_t)np * 16 * ROWB + kfo);

#pragma unroll
            for (int mf = 0; mf < 4; ++mf)
#pragma unroll
                for (int nf = 0; nf < 8; ++nf) {
                    const int s = (nf & 1) * 2;
                    mma_f16(acc[mf][nf], a[mf], b[nf >> 1][s], b[nf >> 1][s + 1]);
                }
        }
    }

    // epilogue: /deg, store
#pragma unroll
    for (int mf = 0; mf < 4; ++mf) {
        const int r0 = bm + warp_m + mf * 16 + (lane >> 2);
        const int r1 = r0 + 8;
        float inv0 = 0.f, inv1 = 0.f;
        if (r0 < C) inv0 = 1.f / (float)(__ldg(ptr + r0 + 1) - __ldg(ptr + r0));
        if (r1 < C) inv1 = 1.f / (float)(__ldg(ptr + r1 + 1) - __ldg(ptr + r1));
#pragma unroll
        for (int nf = 0; nf < 8; ++nf) {
            const int col = nblk * 128 + warp_n + nf * 8 + (lane & 3) * 2;
            if (r0 < C) {
                float2 o; o.x = acc[mf][nf][0] * inv0; o.y = acc[mf][nf][1] * inv0;
                *(float2*)(out + (size_t)r0 * DFEAT + col) = o;
            }
            if (r1 < C) {
                float2 o; o.x = acc[mf][nf][2] * inv1; o.y = acc[mf][nf][3] * inv1;
                *(float2*)(out + (size_t)r1 * DFEAT + col) = o;
            }
        }
    }
}

// ---------------------------------------------------------------------------
extern "C" void kernel_launch(void* const* d_in, const int* in_sizes, int n_in,
                              void* d_out, int out_size) {
    const float* x   = (const float*)d_in[0];
    const float* w   = (const float*)d_in[1];
    const int*   ptr = (const int*)d_in[2];
    const int*   idx = (const int*)d_in[3];
    const int*   rel = (const int*)d_in[4];
    float*       out = (float*)d_out;

    const int C    = in_sizes[2] - 1;
    const int nblk = (C + BM - 1) / BM;
    const int xn2  = in_sizes[0] / 2;

    cudaFuncSetAttribute(gemm_kernel,
                         cudaFuncAttributeMaxDynamicSharedMemorySize, SMEMSZ);

    wsplit_kernel<<<(DFEAT * KDIM) / 256, 256>>>(w);
    xconv_kernel<<<(xn2 + 255) / 256, 256>>>(x, xn2);
    sort_kernel<<<(C + 255) / 256, 256>>>(ptr, idx, rel, C);
    agg_kernel<<<(C + 3) / 4, 128>>>(ptr, C);

    dim3 grid(nblk, DFEAT / 128);
    gemm_kernel<<<grid, 128, SMEMSZ>>>(ptr, out, C);
}